// round 5
// baseline (speedup 1.0000x reference)
#include <cuda_runtime.h>
#include <cstdint>

#define N_NODES 100000
#define D       128
#define R       4
#define E       500000
#define RN      (R * N_NODES)   // 400000
#define REDGES  (R * E)         // 2000000
#define NB      782             // scan blocks (512 each): 782*512 >= 400000
#define NTILE   782             // ceil(N_NODES/128)

// ---------------- scratch (static device globals; no runtime allocs) ----------
__device__ int   g_cnti[RN];
__device__ int   g_fill[RN];
__device__ int   g_off[RN];
__device__ int   g_bsum[1024];
__device__ int   g_bscan[1024];
__device__ int   g_esrc[REDGES];                 // CSR-bucketed source ids
__device__ float g_Wt[(R + 1) * D * D];          // [seg][k][n], scaled
__device__ float g_bavg[D];

// =================== helpers ====================================================
__device__ __forceinline__ uint32_t f2tf32(float f) {
    uint32_t u;
    asm("cvt.rna.tf32.f32 %0, %1;" : "=r"(u) : "f"(f));
    return u;
}
__device__ __forceinline__ void mma8(float* c, const uint32_t* a, const uint32_t* b) {
    asm volatile(
        "mma.sync.aligned.m16n8k8.row.col.f32.tf32.tf32.f32 "
        "{%0,%1,%2,%3}, {%4,%5,%6,%7}, {%8,%9}, {%0,%1,%2,%3};"
        : "+f"(c[0]), "+f"(c[1]), "+f"(c[2]), "+f"(c[3])
        : "r"(a[0]), "r"(a[1]), "r"(a[2]), "r"(a[3]), "r"(b[0]), "r"(b[1]));
}

// ---------------- weight precombine: g_Wt[seg][k][n] ---------------------------
__global__ __launch_bounds__(256) void combine_kernel(const float* __restrict__ Ws,
                                                      const float* __restrict__ Wn,
                                                      const float* __restrict__ b) {
    int i = blockIdx.x * blockDim.x + threadIdx.x;
    if (i < (R + 1) * D * D) {
        int seg = i >> 14, rem = i & 16383;
        float v;
        if (seg == 0) {
            v = 0.f;
            #pragma unroll
            for (int r = 0; r < R; r++) v += Ws[r * D * D + rem];
            v *= 0.25f;
        } else {
            v = Wn[(seg - 1) * D * D + rem] * 0.25f;
        }
        g_Wt[i] = v;
    }
    if (i < D) {
        float s = 0.f;
        #pragma unroll
        for (int r = 0; r < R; r++) s += b[r * D + i];
        g_bavg[i] = s * 0.25f;
    }
}

// ---------------- CSR build ----------------------------------------------------
__global__ __launch_bounds__(256) void zero_kernel() {
    int i = blockIdx.x * blockDim.x + threadIdx.x;
    if (i < RN) { g_cnti[i] = 0; g_fill[i] = 0; }
}
__global__ __launch_bounds__(256) void count_kernel(const int* __restrict__ dst) {
    int i = blockIdx.x * blockDim.x + threadIdx.x;
    if (i >= REDGES) return;
    int r = i / E;
    atomicAdd(&g_cnti[r * N_NODES + dst[i]], 1);
}
__global__ __launch_bounds__(512) void scan1_kernel() {
    __shared__ int tmp[512];
    int t = threadIdx.x, i = blockIdx.x * 512 + t;
    int v = (i < RN) ? g_cnti[i] : 0;
    tmp[t] = v;
    __syncthreads();
    for (int o = 1; o < 512; o <<= 1) {
        int a = (t >= o) ? tmp[t - o] : 0;
        __syncthreads();
        tmp[t] += a;
        __syncthreads();
    }
    if (i < RN) g_off[i] = tmp[t] - v;
    if (t == 511) g_bsum[blockIdx.x] = tmp[511];
}
__global__ __launch_bounds__(1024) void scan2_kernel() {
    __shared__ int tmp[1024];
    int t = threadIdx.x;
    int v = (t < NB) ? g_bsum[t] : 0;
    tmp[t] = v;
    __syncthreads();
    for (int o = 1; o < 1024; o <<= 1) {
        int a = (t >= o) ? tmp[t - o] : 0;
        __syncthreads();
        tmp[t] += a;
        __syncthreads();
    }
    if (t < NB) g_bscan[t] = tmp[t] - v;
}
__global__ __launch_bounds__(512) void scan3_kernel() {
    int i = blockIdx.x * 512 + threadIdx.x;
    if (i < RN) g_off[i] += g_bscan[blockIdx.x];
}
__global__ __launch_bounds__(256) void fill_kernel(const int* __restrict__ src,
                                                   const int* __restrict__ dst) {
    int i = blockIdx.x * blockDim.x + threadIdx.x;
    if (i >= REDGES) return;
    int r = i / E;
    int rd = r * N_NODES + dst[i];
    int pos = g_off[rd] + atomicAdd(&g_fill[rd], 1);
    g_esrc[pos] = src[i];
}

// ---------------- fused gather-aggregate + tf32 GEMM ---------------------------
// Per block (128 rows): seg 0 reads x directly; segs 1..4 gather-mean x[s]
// rows into Agg (fp32 smem), then run the proven tf32 mma.sync chunk pipeline.
// smem: Agg 128x132 f32 (67584B) | As 32x136 u32 (17408B) | Bs 32x136 (17408B)
#define SM_AS  67584
#define SM_BS  (67584 + 17408)
#define SM_TOT (67584 + 17408 + 17408)   // 102400

__global__ __launch_bounds__(256) void fused_kernel(const float* __restrict__ x,
                                                    float* __restrict__ out) {
    extern __shared__ char smem[];
    float*    Agg = (float*)smem;                 // [128][132]
    uint32_t* As  = (uint32_t*)(smem + SM_AS);    // [32][136]
    uint32_t* Bs  = (uint32_t*)(smem + SM_BS);    // [32][136]

    int tid  = threadIdx.x;
    int wid  = tid >> 5, lane = tid & 31;
    int qid  = lane >> 2, kid = lane & 3;
    int wm   = wid & 1, wn = wid >> 1;            // 2 x 4 warp grid
    int row0 = blockIdx.x * 128;

    float c[4][4][4];
    #pragma unroll
    for (int mt = 0; mt < 4; mt++)
        #pragma unroll
        for (int nt = 0; nt < 4; nt++)
            #pragma unroll
            for (int j = 0; j < 4; j++) c[mt][nt][j] = 0.f;

    #pragma unroll 1
    for (int seg = 0; seg < R + 1; seg++) {
        if (seg > 0) {
            // ---- gather-aggregate relation seg-1 into Agg (warp per node) ----
            int r = seg - 1;
            #pragma unroll 1
            for (int nn = wid; nn < 128; nn += 8) {
                int node = row0 + nn;
                float4 s0 = make_float4(0.f, 0.f, 0.f, 0.f);
                float4 s1 = make_float4(0.f, 0.f, 0.f, 0.f);
                int cdeg = 0;
                if (node < N_NODES) {
                    int rd = r * N_NODES + node;
                    int base = g_off[rd];
                    cdeg = g_cnti[rd];
                    int e = 0;
                    for (; e + 2 <= cdeg; e += 2) {
                        int sa = g_esrc[base + e];
                        int sb = g_esrc[base + e + 1];
                        float4 va = *(const float4*)(x + (size_t)sa * D + lane * 4);
                        float4 vb = *(const float4*)(x + (size_t)sb * D + lane * 4);
                        s0.x += va.x; s0.y += va.y; s0.z += va.z; s0.w += va.w;
                        s1.x += vb.x; s1.y += vb.y; s1.z += vb.z; s1.w += vb.w;
                    }
                    if (e < cdeg) {
                        int sa = g_esrc[base + e];
                        float4 va = *(const float4*)(x + (size_t)sa * D + lane * 4);
                        s0.x += va.x; s0.y += va.y; s0.z += va.z; s0.w += va.w;
                    }
                }
                float ic = 1.f / fmaxf((float)cdeg, 1.f);
                float4 o;
                o.x = (s0.x + s1.x) * ic;
                o.y = (s0.y + s1.y) * ic;
                o.z = (s0.z + s1.z) * ic;
                o.w = (s0.w + s1.w) * ic;
                *(float4*)&Agg[nn * 132 + lane * 4] = o;
            }
        }
        __syncthreads();

        const float* Bsrc = g_Wt + seg * D * D;
        #pragma unroll 1
        for (int k0 = 0; k0 < D; k0 += 32) {
            __syncthreads();   // previous chunk's mma readers done before overwrite
            // ---- A chunk -> transposed + swizzled tf32 ----
            #pragma unroll
            for (int p = 0; p < 4; p++) {
                int q = tid + p * 256;            // 0..1023
                int row = q >> 3, kq = q & 7;
                float4 v;
                if (seg == 0) {
                    int n = row0 + row;
                    v = (n < N_NODES) ? *(const float4*)(x + (size_t)n * D + k0 + kq * 4)
                                      : make_float4(0.f, 0.f, 0.f, 0.f);
                } else {
                    v = *(const float4*)&Agg[row * 132 + k0 + kq * 4];
                }
                #pragma unroll
                for (int i = 0; i < 4; i++) {
                    int k = kq * 4 + i;
                    float f = (i == 0) ? v.x : (i == 1) ? v.y : (i == 2) ? v.z : v.w;
                    As[k * 136 + (row ^ (((k >> 2) & 3) << 3))] = f2tf32(f);
                }
            }
            // ---- B chunk: 32 k-rows x 128 n ----
            #pragma unroll
            for (int p = 0; p < 4; p++) {
                int q = tid + p * 256;
                int kk = q >> 5, nq = q & 31;
                float4 v = *(const float4*)(Bsrc + (size_t)(k0 + kk) * D + nq * 4);
                uint4 u;
                u.x = f2tf32(v.x); u.y = f2tf32(v.y); u.z = f2tf32(v.z); u.w = f2tf32(v.w);
                *(uint4*)&Bs[kk * 136 + nq * 4] = u;
            }
            __syncthreads();
            // ---- 4 k8 steps, warp tile 64x32 ----
            #pragma unroll
            for (int kk8 = 0; kk8 < 4; kk8++) {
                int k8 = kk8 * 8;
                int C0 = ((2 * kk8) & 3) << 3;
                int C1 = ((2 * kk8 + 1) & 3) << 3;
                uint32_t a[4][4], b[4][2];
                #pragma unroll
                for (int mt = 0; mt < 4; mt++) {
                    int row = wm * 64 + mt * 16 + qid;
                    a[mt][0] = As[(k8 + kid) * 136 + (row ^ C0)];
                    a[mt][1] = As[(k8 + kid) * 136 + ((row + 8) ^ C0)];
                    a[mt][2] = As[(k8 + 4 + kid) * 136 + (row ^ C1)];
                    a[mt][3] = As[(k8 + 4 + kid) * 136 + ((row + 8) ^ C1)];
                }
                #pragma unroll
                for (int nt = 0; nt < 4; nt++) {
                    int col = wn * 32 + nt * 8 + qid;
                    b[nt][0] = Bs[(k8 + kid) * 136 + col];
                    b[nt][1] = Bs[(k8 + 4 + kid) * 136 + col];
                }
                #pragma unroll
                for (int mt = 0; mt < 4; mt++)
                    #pragma unroll
                    for (int nt = 0; nt < 4; nt++)
                        mma8(c[mt][nt], a[mt], b[nt]);
            }
        }
        __syncthreads();   // all mma done before next seg's gather overwrites Agg
    }

    // ---- epilogue: add mean bias, store float2 pairs ----
    #pragma unroll
    for (int mt = 0; mt < 4; mt++) {
        int r0q = row0 + wm * 64 + mt * 16 + qid;
        #pragma unroll
        for (int nt = 0; nt < 4; nt++) {
            int col = wn * 32 + nt * 8 + kid * 2;
            float b0 = g_bavg[col], b1 = g_bavg[col + 1];
            if (r0q < N_NODES) {
                float2 o = make_float2(c[mt][nt][0] + b0, c[mt][nt][1] + b1);
                *(float2*)(out + (size_t)r0q * D + col) = o;
            }
            if (r0q + 8 < N_NODES) {
                float2 o = make_float2(c[mt][nt][2] + b0, c[mt][nt][3] + b1);
                *(float2*)(out + (size_t)(r0q + 8) * D + col) = o;
            }
        }
    }
}

// ---------------- launch --------------------------------------------------------
extern "C" void kernel_launch(void* const* d_in, const int* in_sizes, int n_in,
                              void* d_out, int out_size) {
    const float* x      = (const float*)d_in[0];
    const int*   src    = (const int*)d_in[1];
    const int*   dst    = (const int*)d_in[2];
    const float* Wself  = (const float*)d_in[3];
    const float* Wneigh = (const float*)d_in[4];
    const float* b      = (const float*)d_in[5];
    float* out = (float*)d_out;

    combine_kernel<<<((R + 1) * D * D + 255) / 256, 256>>>(Wself, Wneigh, b);
    zero_kernel<<<(RN + 255) / 256, 256>>>();
    count_kernel<<<(REDGES + 255) / 256, 256>>>(dst);
    scan1_kernel<<<NB, 512>>>();
    scan2_kernel<<<1, 1024>>>();
    scan3_kernel<<<NB, 512>>>();
    fill_kernel<<<(REDGES + 255) / 256, 256>>>(src, dst);

    cudaFuncSetAttribute(fused_kernel, cudaFuncAttributeMaxDynamicSharedMemorySize, SM_TOT);
    fused_kernel<<<NTILE, 256, SM_TOT>>>(x, out);
    (void)in_sizes; (void)n_in; (void)out_size;
}

// round 6
// speedup vs baseline: 1.1930x; 1.1930x over previous
#include <cuda_runtime.h>
#include <cstdint>

#define N_NODES 100000
#define D       128
#define R       4
#define E       500000
#define RN      (R * N_NODES)
#define REDGES  (R * E)
#define NB      782
#define NTILE   782
#define GRID    148

__device__ int   g_cnti[RN];
__device__ int   g_off[RN];      // after fill: END offset (base = end - cnt)
__device__ int   g_bsum[1024];
__device__ int   g_bscan[1024];
__device__ int   g_esrc[REDGES];
__device__ float g_Wt[(R + 1) * D * D];
__device__ float g_bavg[D];

__device__ __forceinline__ uint32_t f2tf32(float f) {
    uint32_t u;
    asm("cvt.rna.tf32.f32 %0, %1;" : "=r"(u) : "f"(f));
    return u;
}
__device__ __forceinline__ void mma8(float* c, const uint32_t* a, const uint32_t* b) {
    asm volatile(
        "mma.sync.aligned.m16n8k8.row.col.f32.tf32.tf32.f32 "
        "{%0,%1,%2,%3}, {%4,%5,%6,%7}, {%8,%9}, {%0,%1,%2,%3};"
        : "+f"(c[0]), "+f"(c[1]), "+f"(c[2]), "+f"(c[3])
        : "r"(a[0]), "r"(a[1]), "r"(a[2]), "r"(a[3]), "r"(b[0]), "r"(b[1]));
}
#define CONS_BAR() asm volatile("bar.sync 1, 256;" ::: "memory")

__global__ __launch_bounds__(256) void combine_kernel(const float* __restrict__ Ws,
                                                      const float* __restrict__ Wn,
                                                      const float* __restrict__ b) {
    int i = blockIdx.x * blockDim.x + threadIdx.x;
    if (i < (R + 1) * D * D) {
        int seg = i >> 14, rem = i & 16383;
        float v;
        if (seg == 0) {
            v = 0.f;
            #pragma unroll
            for (int r = 0; r < R; r++) v += Ws[r * D * D + rem];
            v *= 0.25f;
        } else {
            v = Wn[(seg - 1) * D * D + rem] * 0.25f;
        }
        g_Wt[i] = v;
    }
    if (i < D) {
        float s = 0.f;
        #pragma unroll
        for (int r = 0; r < R; r++) s += b[r * D + i];
        g_bavg[i] = s * 0.25f;
    }
}

__global__ __launch_bounds__(256) void zero_kernel() {
    int i = blockIdx.x * blockDim.x + threadIdx.x;
    if (i < RN) g_cnti[i] = 0;
}
__global__ __launch_bounds__(256) void count_kernel(const int* __restrict__ dst) {
    int i = blockIdx.x * blockDim.x + threadIdx.x;
    if (i >= REDGES) return;
    int r = i / E;
    atomicAdd(&g_cnti[r * N_NODES + dst[i]], 1);
}
__global__ __launch_bounds__(512) void scan1_kernel() {
    __shared__ int tmp[512];
    int t = threadIdx.x, i = blockIdx.x * 512 + t;
    int v = (i < RN) ? g_cnti[i] : 0;
    tmp[t] = v;
    __syncthreads();
    for (int o = 1; o < 512; o <<= 1) {
        int a = (t >= o) ? tmp[t - o] : 0;
        __syncthreads();
        tmp[t] += a;
        __syncthreads();
    }
    if (i < RN) g_off[i] = tmp[t] - v;
    if (t == 511) g_bsum[blockIdx.x] = tmp[511];
}
__global__ __launch_bounds__(1024) void scan2_kernel() {
    __shared__ int tmp[1024];
    int t = threadIdx.x;
    int v = (t < NB) ? g_bsum[t] : 0;
    tmp[t] = v;
    __syncthreads();
    for (int o = 1; o < 1024; o <<= 1) {
        int a = (t >= o) ? tmp[t - o] : 0;
        __syncthreads();
        tmp[t] += a;
        __syncthreads();
    }
    if (t < NB) g_bscan[t] = tmp[t] - v;
}
__global__ __launch_bounds__(512) void scan3_kernel() {
    int i = blockIdx.x * 512 + threadIdx.x;
    if (i < RN) g_off[i] += g_bscan[blockIdx.x];
}
__global__ __launch_bounds__(256) void fill_kernel(const int* __restrict__ src,
                                                   const int* __restrict__ dst) {
    int i = blockIdx.x * blockDim.x + threadIdx.x;
    if (i >= REDGES) return;
    int r = i / E;
    int rd = r * N_NODES + dst[i];
    int pos = atomicAdd(&g_off[rd], 1);
    g_esrc[pos] = src[i];
}

// ---------------- persistent fused kernel --------------------------------------
// Step s (global, per block): covers (tile, seg) pairs in order
//   tile = s / 5, seg = s % 5 relative to this block's tile sequence.
// Producer at step s gathers relation for step s+1's consumer (if that step's
// seg >= 1). Consumer at step s runs MMA for its (tile, seg) using the buffer
// filled at step s-1 (seg>=1) or x directly (seg==0). Accumulators live across
// the 5 segs of a tile; epilogue at seg==4.
#define AGG_BYTES 67584                 // 128 x 132 fp32
#define SM_AS     (2 * AGG_BYTES)
#define SM_BS     (SM_AS + 17408)
#define SM_TOT    (SM_BS + 17408)       // 169984

__global__ __launch_bounds__(512) void fused_kernel(const float* __restrict__ x,
                                                    float* __restrict__ out) {
    extern __shared__ char smem[];
    uint32_t* As = (uint32_t*)(smem + SM_AS);
    uint32_t* Bs = (uint32_t*)(smem + SM_BS);

    int tid = threadIdx.x;
    int wid = tid >> 5, lane = tid & 31;
    bool producer = (wid >= 8);

    int tiles_here = 0;
    for (int t = (int)blockIdx.x; t < NTILE; t += GRID) tiles_here++;
    int nsteps = tiles_here * 5 + 1;          // +1 drain step

    int qid = lane >> 2, kid = lane & 3;
    int wm  = wid & 1, wn = (wid & 7) >> 1;
    float c[4][4][4];

    for (int s = 0; s < nsteps; s++) {
        float* AggP = (float*)(smem + ((s & 1) ? 0 : AGG_BYTES));
        float* AggC = (float*)(smem + ((s & 1) ? AGG_BYTES : 0));

        if (producer) {
            // produce for step s+1 if that step is a relation seg
            int sn = s + 1;
            if (sn < nsteps) {
                int tq = sn / 5, seg = sn % 5;
                if (seg >= 1) {
                    int tile = (int)blockIdx.x + tq * GRID;
                    int r = seg - 1;
                    int row0 = tile * 128;
                    int pw = wid - 8;
                    #pragma unroll 1
                    for (int nn = pw; nn < 128; nn += 8) {
                        int node = row0 + nn;
                        float4 s0 = make_float4(0.f, 0.f, 0.f, 0.f);
                        float4 s1 = make_float4(0.f, 0.f, 0.f, 0.f);
                        float4 s2 = make_float4(0.f, 0.f, 0.f, 0.f);
                        float4 s3 = make_float4(0.f, 0.f, 0.f, 0.f);
                        int cdeg = 0;
                        if (node < N_NODES) {
                            int rd = r * N_NODES + node;
                            cdeg = g_cnti[rd];
                            int base = g_off[rd] - cdeg;
                            int e = 0;
                            for (; e + 4 <= cdeg; e += 4) {
                                int sa = g_esrc[base + e];
                                int sb = g_esrc[base + e + 1];
                                int sc = g_esrc[base + e + 2];
                                int sd = g_esrc[base + e + 3];
                                float4 va = *(const float4*)(x + (size_t)sa * D + lane * 4);
                                float4 vb = *(const float4*)(x + (size_t)sb * D + lane * 4);
                                float4 vc = *(const float4*)(x + (size_t)sc * D + lane * 4);
                                float4 vd = *(const float4*)(x + (size_t)sd * D + lane * 4);
                                s0.x += va.x; s0.y += va.y; s0.z += va.z; s0.w += va.w;
                                s1.x += vb.x; s1.y += vb.y; s1.z += vb.z; s1.w += vb.w;
                                s2.x += vc.x; s2.y += vc.y; s2.z += vc.z; s2.w += vc.w;
                                s3.x += vd.x; s3.y += vd.y; s3.z += vd.z; s3.w += vd.w;
                            }
                            for (; e < cdeg; e++) {
                                int sa = g_esrc[base + e];
                                float4 va = *(const float4*)(x + (size_t)sa * D + lane * 4);
                                s0.x += va.x; s0.y += va.y; s0.z += va.z; s0.w += va.w;
                            }
                        }
                        float ic = 1.f / fmaxf((float)cdeg, 1.f);
                        float4 o;
                        o.x = (s0.x + s1.x + s2.x + s3.x) * ic;
                        o.y = (s0.y + s1.y + s2.y + s3.y) * ic;
                        o.z = (s0.z + s1.z + s2.z + s3.z) * ic;
                        o.w = (s0.w + s1.w + s2.w + s3.w) * ic;
                        *(float4*)&AggP[nn * 132 + lane * 4] = o;
                    }
                }
            }
        } else {
            if (s >= 0 && s < nsteps - 1) {      // last step is drain-only
                int tq = s / 5, seg = s % 5;
                int tile = (int)blockIdx.x + tq * GRID;
                int row0 = tile * 128;
                if (seg == 0) {
                    #pragma unroll
                    for (int mt = 0; mt < 4; mt++)
                        #pragma unroll
                        for (int nt = 0; nt < 4; nt++)
                            #pragma unroll
                            for (int j = 0; j < 4; j++) c[mt][nt][j] = 0.f;
                }
                const float* Bsrc = g_Wt + seg * D * D;
                #pragma unroll 1
                for (int k0 = 0; k0 < D; k0 += 32) {
                    CONS_BAR();
                    #pragma unroll
                    for (int p = 0; p < 4; p++) {
                        int q = tid + p * 256;
                        int row = q >> 3, kq = q & 7;
                        float4 v;
                        if (seg == 0) {
                            int n = row0 + row;
                            v = (n < N_NODES)
                                ? *(const float4*)(x + (size_t)n * D + k0 + kq * 4)
                                : make_float4(0.f, 0.f, 0.f, 0.f);
                        } else {
                            v = *(const float4*)&AggC[row * 132 + k0 + kq * 4];
                        }
                        #pragma unroll
                        for (int i = 0; i < 4; i++) {
                            int k = kq * 4 + i;
                            float f = (i == 0) ? v.x : (i == 1) ? v.y
                                     : (i == 2) ? v.z : v.w;
                            As[k * 136 + (row ^ (((k >> 2) & 3) << 3))] = f2tf32(f);
                        }
                    }
                    #pragma unroll
                    for (int p = 0; p < 4; p++) {
                        int q = tid + p * 256;
                        int kk = q >> 5, nq = q & 31;
                        float4 v = *(const float4*)(Bsrc + (size_t)(k0 + kk) * D + nq * 4);
                        uint4 u;
                        u.x = f2tf32(v.x); u.y = f2tf32(v.y);
                        u.z = f2tf32(v.z); u.w = f2tf32(v.w);
                        *(uint4*)&Bs[kk * 136 + nq * 4] = u;
                    }
                    CONS_BAR();
                    #pragma unroll
                    for (int kk8 = 0; kk8 < 4; kk8++) {
                        int k8 = kk8 * 8;
                        int C0 = ((2 * kk8) & 3) << 3;
                        int C1 = ((2 * kk8 + 1) & 3) << 3;
                        uint32_t a[4][4], b[4][2];
                        #pragma unroll
                        for (int mt = 0; mt < 4; mt++) {
                            int row = wm * 64 + mt * 16 + qid;
                            a[mt][0] = As[(k8 + kid) * 136 + (row ^ C0)];
                            a[mt][1] = As[(k8 + kid) * 136 + ((row + 8) ^ C0)];
                            a[mt][2] = As[(k8 + 4 + kid) * 136 + (row ^ C1)];
                            a[mt][3] = As[(k8 + 4 + kid) * 136 + ((row + 8) ^ C1)];
                        }
                        #pragma unroll
                        for (int nt = 0; nt < 4; nt++) {
                            int col = wn * 32 + nt * 8 + qid;
                            b[nt][0] = Bs[(k8 + kid) * 136 + col];
                            b[nt][1] = Bs[(k8 + 4 + kid) * 136 + col];
                        }
                        #pragma unroll
                        for (int mt = 0; mt < 4; mt++)
                            #pragma unroll
                            for (int nt = 0; nt < 4; nt++)
                                mma8(c[mt][nt], a[mt], b[nt]);
                    }
                }
                if (seg == R) {
                    #pragma unroll
                    for (int mt = 0; mt < 4; mt++) {
                        int r0q = row0 + wm * 64 + mt * 16 + qid;
                        #pragma unroll
                        for (int nt = 0; nt < 4; nt++) {
                            int col = wn * 32 + nt * 8 + kid * 2;
                            float b0 = g_bavg[col], b1 = g_bavg[col + 1];
                            if (r0q < N_NODES) {
                                float2 o = make_float2(c[mt][nt][0] + b0,
                                                       c[mt][nt][1] + b1);
                                *(float2*)(out + (size_t)r0q * D + col) = o;
                            }
                            if (r0q + 8 < N_NODES) {
                                float2 o = make_float2(c[mt][nt][2] + b0,
                                                       c[mt][nt][3] + b1);
                                *(float2*)(out + (size_t)(r0q + 8) * D + col) = o;
                            }
                        }
                    }
                }
            }
        }
        __syncthreads();   // step boundary: buffer handoff
    }
}

extern "C" void kernel_launch(void* const* d_in, const int* in_sizes, int n_in,
                              void* d_out, int out_size) {
    const float* x      = (const float*)d_in[0];
    const int*   src    = (const int*)d_in[1];
    const int*   dst    = (const int*)d_in[2];
    const float* Wself  = (const float*)d_in[3];
    const float* Wneigh = (const float*)d_in[4];
    const float* b      = (const float*)d_in[5];
    float* out = (float*)d_out;

    combine_kernel<<<((R + 1) * D * D + 255) / 256, 256>>>(Wself, Wneigh, b);
    zero_kernel<<<(RN + 255) / 256, 256>>>();
    count_kernel<<<(REDGES + 255) / 256, 256>>>(dst);
    scan1_kernel<<<NB, 512>>>();
    scan2_kernel<<<1, 1024>>>();
    scan3_kernel<<<NB, 512>>>();
    fill_kernel<<<(REDGES + 255) / 256, 256>>>(src, dst);

    cudaFuncSetAttribute(fused_kernel, cudaFuncAttributeMaxDynamicSharedMemorySize, SM_TOT);
    fused_kernel<<<GRID, 512, SM_TOT>>>(x, out);
    (void)in_sizes; (void)n_in; (void)out_size;
}

// round 7
// speedup vs baseline: 1.3607x; 1.1405x over previous
#include <cuda_runtime.h>
#include <cstdint>

#define N_NODES 100000
#define D       128
#define R       4
#define E       500000
#define RN      (R * N_NODES)
#define REDGES  (R * E)
#define NB      782
#define NTILE   782

// ---------------- scratch (static device globals; no runtime allocs) ----------
__device__ float g_neigh[(size_t)R * N_NODES * D];   // mean-aggregated neighbors
__device__ int   g_cnti[RN];
__device__ int   g_off[RN];      // after fill: END offset (base = end - cnt)
__device__ int   g_bsum[1024];
__device__ int   g_bscan[1024];
__device__ int   g_esrc[REDGES];
__device__ float g_Wt[(R + 1) * D * D];   // [seg][k][n], scaled
__device__ float g_bavg[D];

// =================== helpers ====================================================
__device__ __forceinline__ uint32_t f2tf32(float f) {
    uint32_t u;
    asm("cvt.rna.tf32.f32 %0, %1;" : "=r"(u) : "f"(f));
    return u;
}
__device__ __forceinline__ void mma8(float* c, const uint32_t* a, const uint32_t* b) {
    asm volatile(
        "mma.sync.aligned.m16n8k8.row.col.f32.tf32.tf32.f32 "
        "{%0,%1,%2,%3}, {%4,%5,%6,%7}, {%8,%9}, {%0,%1,%2,%3};"
        : "+f"(c[0]), "+f"(c[1]), "+f"(c[2]), "+f"(c[3])
        : "r"(a[0]), "r"(a[1]), "r"(a[2]), "r"(a[3]), "r"(b[0]), "r"(b[1]));
}

// ---------------- weight precombine: g_Wt[seg][k][n] ---------------------------
__global__ __launch_bounds__(256) void combine_kernel(const float* __restrict__ Ws,
                                                      const float* __restrict__ Wn,
                                                      const float* __restrict__ b) {
    int i = blockIdx.x * blockDim.x + threadIdx.x;
    if (i < (R + 1) * D * D) {
        int seg = i >> 14, rem = i & 16383;
        float v;
        if (seg == 0) {
            v = 0.f;
            #pragma unroll
            for (int r = 0; r < R; r++) v += Ws[r * D * D + rem];
            v *= 0.25f;
        } else {
            v = Wn[(seg - 1) * D * D + rem] * 0.25f;
        }
        g_Wt[i] = v;
    }
    if (i < D) {
        float s = 0.f;
        #pragma unroll
        for (int r = 0; r < R; r++) s += b[r * D + i];
        g_bavg[i] = s * 0.25f;
    }
}

// ---------------- CSR build ----------------------------------------------------
__global__ __launch_bounds__(256) void zero_kernel() {
    int i = blockIdx.x * blockDim.x + threadIdx.x;
    if (i < RN) g_cnti[i] = 0;
}
__global__ __launch_bounds__(256) void count_kernel(const int* __restrict__ dst) {
    int i = blockIdx.x * blockDim.x + threadIdx.x;
    if (i >= REDGES) return;
    int r = i / E;
    atomicAdd(&g_cnti[r * N_NODES + dst[i]], 1);
}
__global__ __launch_bounds__(512) void scan1_kernel() {
    __shared__ int tmp[512];
    int t = threadIdx.x, i = blockIdx.x * 512 + t;
    int v = (i < RN) ? g_cnti[i] : 0;
    tmp[t] = v;
    __syncthreads();
    for (int o = 1; o < 512; o <<= 1) {
        int a = (t >= o) ? tmp[t - o] : 0;
        __syncthreads();
        tmp[t] += a;
        __syncthreads();
    }
    if (i < RN) g_off[i] = tmp[t] - v;
    if (t == 511) g_bsum[blockIdx.x] = tmp[511];
}
__global__ __launch_bounds__(1024) void scan2_kernel() {
    __shared__ int tmp[1024];
    int t = threadIdx.x;
    int v = (t < NB) ? g_bsum[t] : 0;
    tmp[t] = v;
    __syncthreads();
    for (int o = 1; o < 1024; o <<= 1) {
        int a = (t >= o) ? tmp[t - o] : 0;
        __syncthreads();
        tmp[t] += a;
        __syncthreads();
    }
    if (t < NB) g_bscan[t] = tmp[t] - v;
}
__global__ __launch_bounds__(512) void scan3_kernel() {
    int i = blockIdx.x * 512 + threadIdx.x;
    if (i < RN) g_off[i] += g_bscan[blockIdx.x];
}
__global__ __launch_bounds__(256) void fill_kernel(const int* __restrict__ src,
                                                   const int* __restrict__ dst) {
    int i = blockIdx.x * blockDim.x + threadIdx.x;
    if (i >= REDGES) return;
    int r = i / E;
    int rd = r * N_NODES + dst[i];
    int pos = atomicAdd(&g_off[rd], 1);
    g_esrc[pos] = src[i];
}

// ---------------- aggregate: one warp per (relation,node) ----------------------
__global__ __launch_bounds__(256) void aggregate_kernel(const float* __restrict__ x) {
    int gw = (int)(((size_t)blockIdx.x * blockDim.x + threadIdx.x) >> 5);
    int lane = threadIdx.x & 31;
    if (gw >= RN) return;

    int cdeg = g_cnti[gw];
    int base = g_off[gw] - cdeg;

    float4 s0 = make_float4(0.f, 0.f, 0.f, 0.f);
    float4 s1 = make_float4(0.f, 0.f, 0.f, 0.f);
    float4 s2 = make_float4(0.f, 0.f, 0.f, 0.f);
    float4 s3 = make_float4(0.f, 0.f, 0.f, 0.f);
    int e = 0;
    for (; e + 4 <= cdeg; e += 4) {
        int sa = g_esrc[base + e];
        int sb = g_esrc[base + e + 1];
        int sc = g_esrc[base + e + 2];
        int sd = g_esrc[base + e + 3];
        float4 va = *(const float4*)(x + (size_t)sa * D + lane * 4);
        float4 vb = *(const float4*)(x + (size_t)sb * D + lane * 4);
        float4 vc = *(const float4*)(x + (size_t)sc * D + lane * 4);
        float4 vd = *(const float4*)(x + (size_t)sd * D + lane * 4);
        s0.x += va.x; s0.y += va.y; s0.z += va.z; s0.w += va.w;
        s1.x += vb.x; s1.y += vb.y; s1.z += vb.z; s1.w += vb.w;
        s2.x += vc.x; s2.y += vc.y; s2.z += vc.z; s2.w += vc.w;
        s3.x += vd.x; s3.y += vd.y; s3.z += vd.z; s3.w += vd.w;
    }
    for (; e < cdeg; e++) {
        int sa = g_esrc[base + e];
        float4 va = *(const float4*)(x + (size_t)sa * D + lane * 4);
        s0.x += va.x; s0.y += va.y; s0.z += va.z; s0.w += va.w;
    }
    float ic = 1.f / fmaxf((float)cdeg, 1.f);
    float4 o;
    o.x = (s0.x + s1.x + s2.x + s3.x) * ic;
    o.y = (s0.y + s1.y + s2.y + s3.y) * ic;
    o.z = (s0.z + s1.z + s2.z + s3.z) * ic;
    o.w = (s0.w + s1.w + s2.w + s3.w) * ic;
    // streaming store: don't evict L2-resident x
    __stcs((float4*)(g_neigh + (size_t)gw * D + lane * 4), o);
}

// ---------------- tf32 GEMM, double-buffered staging ---------------------------
// 256 threads, tile 128x128, warp tile 64x32 (8 warps, 2x4). 20 chunks
// (5 segs x 4 k-chunks of 32). Per chunk: LDG next -> MMA cur -> STS next -> sync.
// smem: As[2][32][136] u32 | Bs[2][32][136] u32  = 69632 B (dynamic)
#define CHUNK_U32 (32 * 136)
#define SM_GEMM   (4 * CHUNK_U32 * 4)    // 69632

__global__ __launch_bounds__(256) void gemm_kernel(const float* __restrict__ x,
                                                   float* __restrict__ out) {
    extern __shared__ uint32_t sm[];
    uint32_t* Asb[2] = { sm, sm + CHUNK_U32 };
    uint32_t* Bsb[2] = { sm + 2 * CHUNK_U32, sm + 3 * CHUNK_U32 };

    int tid  = threadIdx.x;
    int wid  = tid >> 5, lane = tid & 31;
    int qid  = lane >> 2, kid = lane & 3;
    int wm   = wid & 1, wn = wid >> 1;
    int row0 = blockIdx.x * 128;

    float c[4][4][4];
    #pragma unroll
    for (int mt = 0; mt < 4; mt++)
        #pragma unroll
        for (int nt = 0; nt < 4; nt++)
            #pragma unroll
            for (int j = 0; j < 4; j++) c[mt][nt][j] = 0.f;

    float4 va[4], vb[4];

    // staging index precompute
    int rowA[4], kqA[4], kkB[4], nqB[4];
    #pragma unroll
    for (int p = 0; p < 4; p++) {
        int q = tid + p * 256;
        rowA[p] = q >> 3;  kqA[p] = q & 7;
        kkB[p]  = q >> 5;  nqB[p] = q & 31;
    }

    auto load_chunk = [&](int ch) {
        int seg = ch >> 2, k0 = (ch & 3) * 32;
        const float* Bsrc = g_Wt + seg * D * D;
        #pragma unroll
        for (int p = 0; p < 4; p++) {
            int n = row0 + rowA[p];
            if (seg == 0) {
                va[p] = (n < N_NODES)
                    ? *(const float4*)(x + (size_t)n * D + k0 + kqA[p] * 4)
                    : make_float4(0.f, 0.f, 0.f, 0.f);
            } else {
                va[p] = (n < N_NODES)
                    ? __ldcs((const float4*)(g_neigh +
                        ((size_t)(seg - 1) * N_NODES + n) * D + k0 + kqA[p] * 4))
                    : make_float4(0.f, 0.f, 0.f, 0.f);
            }
            vb[p] = *(const float4*)(Bsrc + (size_t)(k0 + kkB[p]) * D + nqB[p] * 4);
        }
    };
    auto store_chunk = [&](int buf) {
        uint32_t* As = Asb[buf];
        uint32_t* Bs = Bsb[buf];
        #pragma unroll
        for (int p = 0; p < 4; p++) {
            float f[4] = { va[p].x, va[p].y, va[p].z, va[p].w };
            #pragma unroll
            for (int i = 0; i < 4; i++) {
                int k = kqA[p] * 4 + i;
                As[k * 136 + (rowA[p] ^ (((k >> 2) & 3) << 3))] = f2tf32(f[i]);
            }
            uint4 u;
            u.x = f2tf32(vb[p].x); u.y = f2tf32(vb[p].y);
            u.z = f2tf32(vb[p].z); u.w = f2tf32(vb[p].w);
            *(uint4*)&Bs[kkB[p] * 136 + nqB[p] * 4] = u;
        }
    };

    load_chunk(0);
    store_chunk(0);
    __syncthreads();

    #pragma unroll 1
    for (int ch = 0; ch < 20; ch++) {
        int cur = ch & 1;
        if (ch + 1 < 20) load_chunk(ch + 1);        // LDG in flight during MMA

        uint32_t* As = Asb[cur];
        uint32_t* Bs = Bsb[cur];
        #pragma unroll
        for (int kk8 = 0; kk8 < 4; kk8++) {
            int k8 = kk8 * 8;
            int C0 = ((2 * kk8) & 3) << 3;
            int C1 = ((2 * kk8 + 1) & 3) << 3;
            uint32_t a[4][4], b[4][2];
            #pragma unroll
            for (int mt = 0; mt < 4; mt++) {
                int row = wm * 64 + mt * 16 + qid;
                a[mt][0] = As[(k8 + kid) * 136 + (row ^ C0)];
                a[mt][1] = As[(k8 + kid) * 136 + ((row + 8) ^ C0)];
                a[mt][2] = As[(k8 + 4 + kid) * 136 + (row ^ C1)];
                a[mt][3] = As[(k8 + 4 + kid) * 136 + ((row + 8) ^ C1)];
            }
            #pragma unroll
            for (int nt = 0; nt < 4; nt++) {
                int col = wn * 32 + nt * 8 + qid;
                b[nt][0] = Bs[(k8 + kid) * 136 + col];
                b[nt][1] = Bs[(k8 + 4 + kid) * 136 + col];
            }
            #pragma unroll
            for (int mt = 0; mt < 4; mt++)
                #pragma unroll
                for (int nt = 0; nt < 4; nt++)
                    mma8(c[mt][nt], a[mt], b[nt]);
        }

        if (ch + 1 < 20) {
            store_chunk(cur ^ 1);
            __syncthreads();
        }
    }

    // ---- epilogue: add mean bias, store float2 pairs ----
    #pragma unroll
    for (int mt = 0; mt < 4; mt++) {
        int r0q = row0 + wm * 64 + mt * 16 + qid;
        #pragma unroll
        for (int nt = 0; nt < 4; nt++) {
            int col = wn * 32 + nt * 8 + kid * 2;
            float b0 = g_bavg[col], b1 = g_bavg[col + 1];
            if (r0q < N_NODES) {
                float2 o = make_float2(c[mt][nt][0] + b0, c[mt][nt][1] + b1);
                *(float2*)(out + (size_t)r0q * D + col) = o;
            }
            if (r0q + 8 < N_NODES) {
                float2 o = make_float2(c[mt][nt][2] + b0, c[mt][nt][3] + b1);
                *(float2*)(out + (size_t)(r0q + 8) * D + col) = o;
            }
        }
    }
}

// ---------------- launch --------------------------------------------------------
extern "C" void kernel_launch(void* const* d_in, const int* in_sizes, int n_in,
                              void* d_out, int out_size) {
    const float* x      = (const float*)d_in[0];
    const int*   src    = (const int*)d_in[1];
    const int*   dst    = (const int*)d_in[2];
    const float* Wself  = (const float*)d_in[3];
    const float* Wneigh = (const float*)d_in[4];
    const float* b      = (const float*)d_in[5];
    float* out = (float*)d_out;

    combine_kernel<<<((R + 1) * D * D + 255) / 256, 256>>>(Wself, Wneigh, b);
    zero_kernel<<<(RN + 255) / 256, 256>>>();
    count_kernel<<<(REDGES + 255) / 256, 256>>>(dst);
    scan1_kernel<<<NB, 512>>>();
    scan2_kernel<<<1, 1024>>>();
    scan3_kernel<<<NB, 512>>>();
    fill_kernel<<<(REDGES + 255) / 256, 256>>>(src, dst);
    aggregate_kernel<<<(RN * 32 + 255) / 256, 256>>>(x);

    cudaFuncSetAttribute(gemm_kernel, cudaFuncAttributeMaxDynamicSharedMemorySize, SM_GEMM);
    gemm_kernel<<<NTILE, 256, SM_GEMM>>>(x, out);
    (void)in_sizes; (void)n_in; (void)out_size;
}

// round 8
// speedup vs baseline: 1.4422x; 1.0599x over previous
#include <cuda_runtime.h>
#include <cstdint>

#define N_NODES 100000
#define D       128
#define R       4
#define E       500000
#define RN      (R * N_NODES)
#define REDGES  (R * E)
#define NB      782
#define NTILE   782

// ---------------- scratch (static device globals; no runtime allocs) ----------
__device__ float g_neigh[(size_t)R * N_NODES * D];   // mean-aggregated neighbors
__device__ int   g_cnti[RN];
__device__ int   g_off[RN];      // after fill: END offset (base = end - cnt)
__device__ int   g_bsum[1024];
__device__ int   g_bscan[1024];
__device__ int   g_esrc[REDGES];
__device__ float g_Wt[(R + 1) * D * D];   // [seg][k][n], scaled
__device__ float g_bavg[D];

// =================== helpers ====================================================
__device__ __forceinline__ uint32_t f2tf32(float f) {
    uint32_t u;
    asm("cvt.rna.tf32.f32 %0, %1;" : "=r"(u) : "f"(f));
    return u;
}
__device__ __forceinline__ void mma8(float* c, const uint32_t* a, const uint32_t* b) {
    asm volatile(
        "mma.sync.aligned.m16n8k8.row.col.f32.tf32.tf32.f32 "
        "{%0,%1,%2,%3}, {%4,%5,%6,%7}, {%8,%9}, {%0,%1,%2,%3};"
        : "+f"(c[0]), "+f"(c[1]), "+f"(c[2]), "+f"(c[3])
        : "r"(a[0]), "r"(a[1]), "r"(a[2]), "r"(a[3]), "r"(b[0]), "r"(b[1]));
}
__device__ __forceinline__ uint32_t smem_u32(const void* p) {
    uint32_t a;
    asm("{ .reg .u64 t; cvta.to.shared.u64 t, %1; cvt.u32.u64 %0, t; }" : "=r"(a) : "l"(p));
    return a;
}
__device__ __forceinline__ void cp16(uint32_t dst, const void* src, bool ok) {
    int sz = ok ? 16 : 0;
    asm volatile("cp.async.cg.shared.global [%0], [%1], 16, %2;"
                 :: "r"(dst), "l"(src), "r"(sz) : "memory");
}
#define CP_COMMIT() asm volatile("cp.async.commit_group;" ::: "memory")
#define CP_WAIT(n)  asm volatile("cp.async.wait_group %0;" :: "n"(n) : "memory")

// ---------------- weight precombine: g_Wt[seg][k][n] ---------------------------
__global__ __launch_bounds__(256) void combine_kernel(const float* __restrict__ Ws,
                                                      const float* __restrict__ Wn,
                                                      const float* __restrict__ b) {
    int i = blockIdx.x * blockDim.x + threadIdx.x;
    if (i < (R + 1) * D * D) {
        int seg = i >> 14, rem = i & 16383;
        float v;
        if (seg == 0) {
            v = 0.f;
            #pragma unroll
            for (int r = 0; r < R; r++) v += Ws[r * D * D + rem];
            v *= 0.25f;
        } else {
            v = Wn[(seg - 1) * D * D + rem] * 0.25f;
        }
        g_Wt[i] = v;
    }
    if (i < D) {
        float s = 0.f;
        #pragma unroll
        for (int r = 0; r < R; r++) s += b[r * D + i];
        g_bavg[i] = s * 0.25f;
    }
}

// ---------------- CSR build ----------------------------------------------------
__global__ __launch_bounds__(256) void zero_kernel() {
    int i = blockIdx.x * blockDim.x + threadIdx.x;
    if (i < RN) g_cnti[i] = 0;
}
__global__ __launch_bounds__(256) void count_kernel(const int* __restrict__ dst) {
    int i = blockIdx.x * blockDim.x + threadIdx.x;
    if (i >= REDGES) return;
    int r = i / E;
    atomicAdd(&g_cnti[r * N_NODES + dst[i]], 1);
}
__global__ __launch_bounds__(512) void scan1_kernel() {
    __shared__ int tmp[512];
    int t = threadIdx.x, i = blockIdx.x * 512 + t;
    int v = (i < RN) ? g_cnti[i] : 0;
    tmp[t] = v;
    __syncthreads();
    for (int o = 1; o < 512; o <<= 1) {
        int a = (t >= o) ? tmp[t - o] : 0;
        __syncthreads();
        tmp[t] += a;
        __syncthreads();
    }
    if (i < RN) g_off[i] = tmp[t] - v;
    if (t == 511) g_bsum[blockIdx.x] = tmp[511];
}
__global__ __launch_bounds__(1024) void scan2_kernel() {
    __shared__ int tmp[1024];
    int t = threadIdx.x;
    int v = (t < NB) ? g_bsum[t] : 0;
    tmp[t] = v;
    __syncthreads();
    for (int o = 1; o < 1024; o <<= 1) {
        int a = (t >= o) ? tmp[t - o] : 0;
        __syncthreads();
        tmp[t] += a;
        __syncthreads();
    }
    if (t < NB) g_bscan[t] = tmp[t] - v;
}
__global__ __launch_bounds__(512) void scan3_kernel() {
    int i = blockIdx.x * 512 + threadIdx.x;
    if (i < RN) g_off[i] += g_bscan[blockIdx.x];
}
__global__ __launch_bounds__(256) void fill_kernel(const int* __restrict__ src,
                                                   const int* __restrict__ dst) {
    int i = blockIdx.x * blockDim.x + threadIdx.x;
    if (i >= REDGES) return;
    int r = i / E;
    int rd = r * N_NODES + dst[i];
    int pos = atomicAdd(&g_off[rd], 1);
    g_esrc[pos] = src[i];
}

// ---------------- aggregate: one warp per (relation,node) ----------------------
__global__ __launch_bounds__(256) void aggregate_kernel(const float* __restrict__ x) {
    int gw = (int)(((size_t)blockIdx.x * blockDim.x + threadIdx.x) >> 5);
    int lane = threadIdx.x & 31;
    if (gw >= RN) return;

    int cdeg = g_cnti[gw];
    int base = g_off[gw] - cdeg;

    float4 s0 = make_float4(0.f, 0.f, 0.f, 0.f);
    float4 s1 = make_float4(0.f, 0.f, 0.f, 0.f);
    float4 s2 = make_float4(0.f, 0.f, 0.f, 0.f);
    float4 s3 = make_float4(0.f, 0.f, 0.f, 0.f);
    int e = 0;
    for (; e + 4 <= cdeg; e += 4) {
        int sa = g_esrc[base + e];
        int sb = g_esrc[base + e + 1];
        int sc = g_esrc[base + e + 2];
        int sd = g_esrc[base + e + 3];
        float4 va = *(const float4*)(x + (size_t)sa * D + lane * 4);
        float4 vb = *(const float4*)(x + (size_t)sb * D + lane * 4);
        float4 vc = *(const float4*)(x + (size_t)sc * D + lane * 4);
        float4 vd = *(const float4*)(x + (size_t)sd * D + lane * 4);
        s0.x += va.x; s0.y += va.y; s0.z += va.z; s0.w += va.w;
        s1.x += vb.x; s1.y += vb.y; s1.z += vb.z; s1.w += vb.w;
        s2.x += vc.x; s2.y += vc.y; s2.z += vc.z; s2.w += vc.w;
        s3.x += vd.x; s3.y += vd.y; s3.z += vd.z; s3.w += vd.w;
    }
    for (; e < cdeg; e++) {
        int sa = g_esrc[base + e];
        float4 va = *(const float4*)(x + (size_t)sa * D + lane * 4);
        s0.x += va.x; s0.y += va.y; s0.z += va.z; s0.w += va.w;
    }
    float ic = 1.f / fmaxf((float)cdeg, 1.f);
    float4 o;
    o.x = (s0.x + s1.x + s2.x + s3.x) * ic;
    o.y = (s0.y + s1.y + s2.y + s3.y) * ic;
    o.z = (s0.z + s1.z + s2.z + s3.z) * ic;
    o.w = (s0.w + s1.w + s2.w + s3.w) * ic;
    *(float4*)(g_neigh + (size_t)gw * D + lane * 4) = o;
}

// ---------------- tf32 GEMM with cp.async 3-stage pipeline ---------------------
// 256 threads, tile 128x128, warp tile 64x32 (8 warps 2x4). 20 chunks
// (5 segs x 4 k-chunks of 32). Raw fp32 staged via cp.async (no register
// residency); cvt.rna.tf32 after fragment LDS (same rounding as before).
// A stage: row-major [128][36] f32 (18432 B) — fragment LDS conflict-free
//   (bank = (4*qid + kid) mod 32). B stage: [32][132] f32 (16896 B).
#define A_BYTES 18432
#define STAGE_B 35328
#define SM_GEMM (3 * STAGE_B)    // 105984

__global__ __launch_bounds__(256, 2) void gemm_kernel(const float* __restrict__ x,
                                                      float* __restrict__ out) {
    extern __shared__ char smem[];
    uint32_t sbase = smem_u32(smem);

    int tid  = threadIdx.x;
    int wid  = tid >> 5, lane = tid & 31;
    int qid  = lane >> 2, kid = lane & 3;
    int wm   = wid & 1, wn = wid >> 1;
    int row0 = blockIdx.x * 128;

    float c[4][4][4];
    #pragma unroll
    for (int mt = 0; mt < 4; mt++)
        #pragma unroll
        for (int nt = 0; nt < 4; nt++)
            #pragma unroll
            for (int j = 0; j < 4; j++) c[mt][nt][j] = 0.f;

    // per-thread copy slots
    int rowA = tid >> 1, fA = (tid & 1) * 4;        // 2 threads per A row, 4x16B each
    int kkB  = tid >> 3, fB = (tid & 7) * 4;        // 8 threads per B k-row, 4x16B each

    auto issue_chunk = [&](int ch, int st) {
        int seg = ch >> 2, k0 = (ch & 3) * 32;
        const float* Abase = (seg == 0) ? x
                           : (g_neigh + (size_t)(seg - 1) * N_NODES * D);
        int n = row0 + rowA;
        bool ok = (n < N_NODES);
        const float* asrc = Abase + (size_t)(ok ? n : 0) * D + k0 + fA * 4;
        uint32_t adst = sbase + st * STAGE_B + rowA * 144 + fA * 16;
        #pragma unroll
        for (int p = 0; p < 4; p++)
            cp16(adst + p * 16, asrc + p * 4, ok);

        const float* bsrc = g_Wt + seg * D * D + (size_t)(k0 + kkB) * D + fB * 4;
        uint32_t bdst = sbase + st * STAGE_B + A_BYTES + kkB * 528 + fB * 16;
        #pragma unroll
        for (int p = 0; p < 4; p++)
            cp16(bdst + p * 16, bsrc + p * 4, true);
        CP_COMMIT();
    };

    issue_chunk(0, 0);
    issue_chunk(1, 1);
    issue_chunk(2, 2);

    #pragma unroll 1
    for (int ch = 0; ch < 20; ch++) {
        int st = ch % 3;
        if (ch <= 16)      CP_WAIT(2);
        else if (ch == 17) CP_WAIT(2);
        else if (ch == 18) CP_WAIT(1);
        else               CP_WAIT(0);
        __syncthreads();

        const float* As = (const float*)(smem + st * STAGE_B);            // [128][36]
        const float* Bs = (const float*)(smem + st * STAGE_B + A_BYTES);  // [32][132]

        #pragma unroll
        for (int kk8 = 0; kk8 < 4; kk8++) {
            int k8 = kk8 * 8;
            uint32_t a[4][4], b[4][2];
            #pragma unroll
            for (int mt = 0; mt < 4; mt++) {
                int row = wm * 64 + mt * 16 + qid;
                a[mt][0] = f2tf32(As[row * 36 + k8 + kid]);
                a[mt][1] = f2tf32(As[(row + 8) * 36 + k8 + kid]);
                a[mt][2] = f2tf32(As[row * 36 + k8 + 4 + kid]);
                a[mt][3] = f2tf32(As[(row + 8) * 36 + k8 + 4 + kid]);
            }
            #pragma unroll
            for (int nt = 0; nt < 4; nt++) {
                int col = wn * 32 + nt * 8 + qid;
                b[nt][0] = f2tf32(Bs[(k8 + kid) * 132 + col]);
                b[nt][1] = f2tf32(Bs[(k8 + 4 + kid) * 132 + col]);
            }
            #pragma unroll
            for (int mt = 0; mt < 4; mt++)
                #pragma unroll
                for (int nt = 0; nt < 4; nt++)
                    mma8(c[mt][nt], a[mt], b[nt]);
        }

        __syncthreads();                 // all readers done before stage reuse
        if (ch + 3 < 20) issue_chunk(ch + 3, st);
    }

    // ---- epilogue: add mean bias, store float2 pairs ----
    #pragma unroll
    for (int mt = 0; mt < 4; mt++) {
        int r0q = row0 + wm * 64 + mt * 16 + qid;
        #pragma unroll
        for (int nt = 0; nt < 4; nt++) {
            int col = wn * 32 + nt * 8 + kid * 2;
            float b0 = g_bavg[col], b1 = g_bavg[col + 1];
            if (r0q < N_NODES) {
                float2 o = make_float2(c[mt][nt][0] + b0, c[mt][nt][1] + b1);
                *(float2*)(out + (size_t)r0q * D + col) = o;
            }
            if (r0q + 8 < N_NODES) {
                float2 o = make_float2(c[mt][nt][2] + b0, c[mt][nt][3] + b1);
                *(float2*)(out + (size_t)(r0q + 8) * D + col) = o;
            }
        }
    }
}

// ---------------- launch --------------------------------------------------------
extern "C" void kernel_launch(void* const* d_in, const int* in_sizes, int n_in,
                              void* d_out, int out_size) {
    const float* x      = (const float*)d_in[0];
    const int*   src    = (const int*)d_in[1];
    const int*   dst    = (const int*)d_in[2];
    const float* Wself  = (const float*)d_in[3];
    const float* Wneigh = (const float*)d_in[4];
    const float* b      = (const float*)d_in[5];
    float* out = (float*)d_out;

    combine_kernel<<<((R + 1) * D * D + 255) / 256, 256>>>(Wself, Wneigh, b);
    zero_kernel<<<(RN + 255) / 256, 256>>>();
    count_kernel<<<(REDGES + 255) / 256, 256>>>(dst);
    scan1_kernel<<<NB, 512>>>();
    scan2_kernel<<<1, 1024>>>();
    scan3_kernel<<<NB, 512>>>();
    fill_kernel<<<(REDGES + 255) / 256, 256>>>(src, dst);
    aggregate_kernel<<<(RN * 32 + 255) / 256, 256>>>(x);

    cudaFuncSetAttribute(gemm_kernel, cudaFuncAttributeMaxDynamicSharedMemorySize, SM_GEMM);
    gemm_kernel<<<NTILE, 256, SM_GEMM>>>(x, out);
    (void)in_sizes; (void)n_in; (void)out_size;
}